// round 7
// baseline (speedup 1.0000x reference)
#include <cuda_runtime.h>
#include <cstdint>

// ===================== problem constants =====================
static constexpr int PB = 16;    // batch
static constexpr int PS = 512;   // S1 = S2
static constexpr int PH = 256;   // hidden
static constexpr int PL = 16;    // perspectives

// main-kernel tiling
static constexpr int TILE_M = 128;                 // i rows per CTA
static constexpr int TILE_N = 128;                 // (j,l) cols per CTA = 8 j * 16 l
static constexpr int KC     = 64;                  // K chunk
static constexpr int NKC    = PH / KC;             // 4 chunks
static constexpr int NT     = (PS * PL) / TILE_N;  // 64 n-tiles
static constexpr int IT     = PS / TILE_M;         // 4 i-tiles

static constexpr int KPAD = 68;    // A row stride (floats): conflict-free frag loads
static constexpr int NPAD = 136;   // B row stride (floats): 136%32=8 -> conflict-free

// scratch for reciprocal weighted norms (device globals: allocation-free)
__device__ float g_rn1[PB * PS * PL];
__device__ float g_rn2[PB * PS * PL];

// ===================== helpers =====================
__device__ __forceinline__ uint32_t f2tf32(float x) {
    uint32_t r;
    asm("cvt.rna.tf32.f32 %0, %1;" : "=r"(r) : "f"(x));
    return r;
}

// m16n8k8 tf32 MMA, D += A*B (fragments per PTX ISA mapping)
__device__ __forceinline__ void mma_tf32(float* c, const uint32_t* a,
                                         uint32_t b0, uint32_t b1) {
    asm volatile(
        "mma.sync.aligned.m16n8k8.row.col.f32.tf32.tf32.f32 "
        "{%0,%1,%2,%3}, {%4,%5,%6,%7}, {%8,%9}, {%0,%1,%2,%3};\n"
        : "+f"(c[0]), "+f"(c[1]), "+f"(c[2]), "+f"(c[3])
        : "r"(a[0]), "r"(a[1]), "r"(a[2]), "r"(a[3]), "r"(b0), "r"(b1));
}

// ===================== kernel 1: reciprocal weighted norms =====================
// one warp per (tensor, b, s): rn[b,s,l] = rsqrt( sum_h (w[l,h]*v[b,s,h])^2 )
__global__ __launch_bounds__(256) void rnorm_kernel(const float* __restrict__ v1,
                                                    const float* __restrict__ v2,
                                                    const float* __restrict__ w) {
    int gw  = blockIdx.x * 8 + (threadIdx.x >> 5);   // 0 .. 16383
    int lid = threadIdx.x & 31;
    const float* v  = (gw < PB * PS) ? v1 : v2;
    float*       op = (gw < PB * PS) ? g_rn1 : g_rn2;
    int idx = gw & (PB * PS - 1);                    // b*512 + s
    int h0  = lid * 8;

    const float4* vp = (const float4*)(v + (size_t)idx * PH + h0);
    float4 va = vp[0], vb = vp[1];

    float keep = 0.f;
#pragma unroll
    for (int l = 0; l < PL; l++) {
        const float4* wp = (const float4*)(w + l * PH + h0);
        float4 wa = wp[0], wb = wp[1];
        float m, s;
        m = wa.x * va.x; s = m * m;
        m = wa.y * va.y; s = fmaf(m, m, s);
        m = wa.z * va.z; s = fmaf(m, m, s);
        m = wa.w * va.w; s = fmaf(m, m, s);
        m = wb.x * vb.x; s = fmaf(m, m, s);
        m = wb.y * vb.y; s = fmaf(m, m, s);
        m = wb.z * vb.z; s = fmaf(m, m, s);
        m = wb.w * vb.w; s = fmaf(m, m, s);
        s += __shfl_xor_sync(0xffffffffu, s, 16);
        s += __shfl_xor_sync(0xffffffffu, s, 8);
        s += __shfl_xor_sync(0xffffffffu, s, 4);
        s += __shfl_xor_sync(0xffffffffu, s, 2);
        s += __shfl_xor_sync(0xffffffffu, s, 1);
        if (lid == l) keep = s;
    }
    if (lid < PL) op[(size_t)idx * PL + lid] = rsqrtf(keep);
}

// ===================== kernel 2: main fused GEMM (mma.sync tf32) =====================
// CTA(b, it, nt): out[b, it*128.., nt*128..], N axis = (j*16 + l).
//   A  = v1 tile, tf32 in smem [128][KPAD], chunked over K, double-buffered
//   B" = (w^2 (.) v2) chunk, tf32 in smem [KC][NPAD] (k-major), double-buffered
//   Epilogue scales by rn1[i,l]*rn2[n], coalesced float2 stores.

// smem float offsets
static constexpr uint32_t FO_A0  = 0;                          // 128*68 = 8704 floats
static constexpr uint32_t FO_A1  = FO_A0 + TILE_M * KPAD;      // 8704
static constexpr uint32_t FO_B0  = FO_A1 + TILE_M * KPAD;      // 64*136 = 8704
static constexpr uint32_t FO_B1  = FO_B0 + KC * NPAD;
static constexpr uint32_t FO_V2  = FO_B1 + KC * NPAD;          // 8*260 = 2080
static constexpr uint32_t FO_W2  = FO_V2 + 8 * 260;            // 16*260 = 4160
static constexpr uint32_t FO_RN1 = FO_W2 + 16 * 260;           // 128*16 = 2048
static constexpr uint32_t FO_RN2 = FO_RN1 + TILE_M * PL;       // 128
static constexpr uint32_t SMEM_FLOATS = FO_RN2 + TILE_N;
static constexpr uint32_t SMEM_BYTES  = SMEM_FLOATS * 4;       // 173,440 B < 227 KB

__global__ void __launch_bounds__(256, 1)
matching_mma(const float* __restrict__ v1, const float* __restrict__ v2,
             const float* __restrict__ w, float* __restrict__ out) {
    extern __shared__ float sm[];

    const int tid = threadIdx.x;
    const int wid = tid >> 5;
    const int lid = tid & 31;
    const int bb  = blockIdx.z;
    const int it  = blockIdx.y;
    const int nt  = blockIdx.x;

    const int wrow = wid >> 1;        // 0..3 -> i offset wrow*32
    const int wcol = wid & 1;         // 0..1 -> n offset wcol*64
    const int iw   = wrow * 32;
    const int nw   = wcol * 64;

    float* v2s  = sm + FO_V2;    // [8][260]
    float* w2s  = sm + FO_W2;    // [16][260]
    float* rn1s = sm + FO_RN1;   // [128][16]
    float* rn2s = sm + FO_RN2;   // [128]

    const int j0 = nt * 8;       // first j row of this n-tile

    // ---- stage raw operands ----
    // w^2 : 16 rows x 256
    for (int idx = tid; idx < PL * (PH / 4); idx += 256) {
        int l = idx >> 6, h4 = idx & 63;
        float4 t = ((const float4*)(w + l * PH))[h4];
        t.x *= t.x; t.y *= t.y; t.z *= t.z; t.w *= t.w;
        *(float4*)&w2s[l * 260 + h4 * 4] = t;
    }
    // v2 rows for this n-tile: 8 x 256
    for (int idx = tid; idx < 8 * (PH / 4); idx += 256) {
        int jj = idx >> 6, h4 = idx & 63;
        float4 t = ((const float4*)(v2 + ((size_t)(bb * PS + j0 + jj)) * PH))[h4];
        *(float4*)&v2s[jj * 260 + h4 * 4] = t;
    }
    // rn1 tile: 2048 contiguous floats
    {
        const float4* src = (const float4*)(g_rn1 + ((size_t)(bb * PS + it * TILE_M)) * PL);
        ((float4*)rn1s)[tid]       = src[tid];
        ((float4*)rn1s)[tid + 256] = src[tid + 256];
    }
    // rn2 tile: 128 contiguous floats
    if (tid < 32) {
        ((float4*)rn2s)[tid] = ((const float4*)(g_rn2 + ((size_t)(bb * PS + j0)) * PL))[tid];
    }
    __syncthreads();

    const float* v1base = v1 + ((size_t)(bb * PS + it * TILE_M)) * PH;

    // chunk builders (each thread: 8 float4 for A, 8 float4 for B)
    auto buildA = [&](int kc, uint32_t* dst) {
        const int hbase = kc * KC;
#pragma unroll
        for (int t = 0; t < 8; t++) {
            int g   = tid + t * 256;        // 0..2047 float4 slots
            int i   = g >> 4;               // 128 rows
            int k   = (g & 15) * 4;         // 0..60
            float4 s = *(const float4*)(v1base + (size_t)i * PH + hbase + k);
            uint4 u;
            u.x = f2tf32(s.x); u.y = f2tf32(s.y); u.z = f2tf32(s.z); u.w = f2tf32(s.w);
            *(uint4*)(dst + i * KPAD + k) = u;
        }
    };
    auto buildB = [&](int kc, uint32_t* dst) {
        const int hbase = kc * KC;
#pragma unroll
        for (int t = 0; t < 8; t++) {
            int g  = tid + t * 256;         // 0..2047
            int k  = g >> 5;                // 0..63 (32 float4 per k-row)
            int n0 = (g & 31) * 4;          // 0..124
            int jj = n0 >> 4;               // j within tile
            int l0 = n0 & 15;               // 0,4,8,12
            int m  = hbase + k;
            float a = v2s[jj * 260 + m];
            uint4 u;
            u.x = f2tf32(a * w2s[(l0 + 0) * 260 + m]);
            u.y = f2tf32(a * w2s[(l0 + 1) * 260 + m]);
            u.z = f2tf32(a * w2s[(l0 + 2) * 260 + m]);
            u.w = f2tf32(a * w2s[(l0 + 3) * 260 + m]);
            *(uint4*)(dst + k * NPAD + n0) = u;
        }
    };

    // build stage 0
    buildA(0, (uint32_t*)(sm + FO_A0));
    buildB(0, (uint32_t*)(sm + FO_B0));
    __syncthreads();

    float acc[2][8][4];
#pragma unroll
    for (int mf = 0; mf < 2; mf++)
#pragma unroll
        for (int nf = 0; nf < 8; nf++)
#pragma unroll
            for (int q = 0; q < 4; q++) acc[mf][nf][q] = 0.f;

    const int arow = lid >> 2;   // 0..7
    const int acol = lid & 3;    // 0..3

    for (int kc = 0; kc < NKC; kc++) {
        const int cur = kc & 1;
        // build next chunk first (LDG/FFMA/STS overlap the LDS/MMA below)
        if (kc + 1 < NKC) {
            buildA(kc + 1, (uint32_t*)(sm + (cur ? FO_A0 : FO_A1)));
            buildB(kc + 1, (uint32_t*)(sm + (cur ? FO_B0 : FO_B1)));
        }
        const uint32_t* As = (const uint32_t*)(sm + (cur ? FO_A1 : FO_A0));
        const uint32_t* Bs = (const uint32_t*)(sm + (cur ? FO_B1 : FO_B0));

#pragma unroll
        for (int ks = 0; ks < KC / 8; ks++) {
            const int k0 = ks * 8;
            uint32_t af[2][4];
#pragma unroll
            for (int mf = 0; mf < 2; mf++) {
                const int r = iw + mf * 16 + arow;
                const int c = k0 + acol;
                af[mf][0] = As[r * KPAD + c];
                af[mf][1] = As[(r + 8) * KPAD + c];
                af[mf][2] = As[r * KPAD + c + 4];
                af[mf][3] = As[(r + 8) * KPAD + c + 4];
            }
#pragma unroll
            for (int nf = 0; nf < 8; nf++) {
                const int cn = nw + nf * 8 + arow;
                uint32_t b0 = Bs[(k0 + acol) * NPAD + cn];
                uint32_t b1 = Bs[(k0 + 4 + acol) * NPAD + cn];
                mma_tf32(acc[0][nf], af[0], b0, b1);
                mma_tf32(acc[1][nf], af[1], b0, b1);
            }
        }
        __syncthreads();
    }

    // ---- epilogue: scale by rn1[i,l] * rn2[n], coalesced float2 stores ----
    {
        const size_t orow0 = (size_t)(bb * PS + it * TILE_M);
        float* obase = out + orow0 * (size_t)(PS * PL) + (size_t)nt * TILE_N;
#pragma unroll
        for (int mf = 0; mf < 2; mf++) {
            const int r0 = iw + mf * 16 + arow;       // local i (and r0+8)
#pragma unroll
            for (int nf = 0; nf < 8; nf++) {
                const int cn = nw + nf * 8 + 2 * acol;  // local n (even)
                const float s2x = rn2s[cn];
                const float s2y = rn2s[cn + 1];
                const int lx = cn & 15, ly = (cn + 1) & 15;
                {
                    const float r1x = rn1s[r0 * 16 + lx];
                    const float r1y = rn1s[r0 * 16 + ly];
                    float2 o;
                    o.x = acc[mf][nf][0] * r1x * s2x;
                    o.y = acc[mf][nf][1] * r1y * s2y;
                    *(float2*)(obase + (size_t)r0 * (PS * PL) + cn) = o;
                }
                {
                    const int r1r = r0 + 8;
                    const float r1x = rn1s[r1r * 16 + lx];
                    const float r1y = rn1s[r1r * 16 + ly];
                    float2 o;
                    o.x = acc[mf][nf][2] * r1x * s2x;
                    o.y = acc[mf][nf][3] * r1y * s2y;
                    *(float2*)(obase + (size_t)r1r * (PS * PL) + cn) = o;
                }
            }
        }
    }
}

// ===================== launch =====================
extern "C" void kernel_launch(void* const* d_in, const int* in_sizes, int n_in,
                              void* d_out, int out_size) {
    const float* v1 = (const float*)d_in[0];
    const float* v2 = (const float*)d_in[1];
    const float* w  = (const float*)d_in[2];
    float* out = (float*)d_out;

    cudaFuncSetAttribute(matching_mma,
                         cudaFuncAttributeMaxDynamicSharedMemorySize, SMEM_BYTES);

    // 2 * PB * PS = 16384 warps, 8 warps per block
    rnorm_kernel<<<2048, 256>>>(v1, v2, w);

    dim3 grid(NT, IT, PB);
    matching_mma<<<grid, 256, SMEM_BYTES>>>(v1, v2, w, out);
}

// round 8
// speedup vs baseline: 1.0345x; 1.0345x over previous
#include <cuda_runtime.h>
#include <cstdint>

// ===================== problem constants =====================
static constexpr int PB = 16;    // batch
static constexpr int PS = 512;   // S1 = S2
static constexpr int PH = 256;   // hidden
static constexpr int PL = 16;    // perspectives

// main-kernel tiling
static constexpr int TILE_M = 128;                 // i rows per CTA
static constexpr int TILE_N = 256;                 // (j,l) cols per CTA = 16 j * 16 l
static constexpr int KC     = 32;                  // K chunk
static constexpr int NKC    = PH / KC;             // 8 chunks
static constexpr int NT     = (PS * PL) / TILE_N;  // 32 n-tiles
static constexpr int IT     = PS / TILE_M;         // 4 i-tiles

static constexpr int KPAD = 36;    // A row stride: (36%32=4) -> frag loads conflict-free
static constexpr int NPAD = 264;   // B row stride: (264%32=8) -> frag loads conflict-free

// scratch for reciprocal weighted norms (device globals: allocation-free)
__device__ float g_rn1[PB * PS * PL];
__device__ float g_rn2[PB * PS * PL];

// ===================== helpers =====================
__device__ __forceinline__ uint32_t f2tf32(float x) {
    uint32_t r;
    asm("cvt.rna.tf32.f32 %0, %1;" : "=r"(r) : "f"(x));
    return r;
}

// m16n8k8 tf32 MMA, D += A*B (fragments per PTX ISA mapping)
__device__ __forceinline__ void mma_tf32(float* c, const uint32_t* a,
                                         uint32_t b0, uint32_t b1) {
    asm volatile(
        "mma.sync.aligned.m16n8k8.row.col.f32.tf32.tf32.f32 "
        "{%0,%1,%2,%3}, {%4,%5,%6,%7}, {%8,%9}, {%0,%1,%2,%3};\n"
        : "+f"(c[0]), "+f"(c[1]), "+f"(c[2]), "+f"(c[3])
        : "r"(a[0]), "r"(a[1]), "r"(a[2]), "r"(a[3]), "r"(b0), "r"(b1));
}

// ===================== kernel 1: reciprocal weighted norms =====================
// one warp per (tensor, b, s): rn[b,s,l] = rsqrt( sum_h (w[l,h]*v[b,s,h])^2 )
__global__ __launch_bounds__(256) void rnorm_kernel(const float* __restrict__ v1,
                                                    const float* __restrict__ v2,
                                                    const float* __restrict__ w) {
    int gw  = blockIdx.x * 8 + (threadIdx.x >> 5);   // 0 .. 16383
    int lid = threadIdx.x & 31;
    const float* v  = (gw < PB * PS) ? v1 : v2;
    float*       op = (gw < PB * PS) ? g_rn1 : g_rn2;
    int idx = gw & (PB * PS - 1);                    // b*512 + s
    int h0  = lid * 8;

    const float4* vp = (const float4*)(v + (size_t)idx * PH + h0);
    float4 va = vp[0], vb = vp[1];

    float keep = 0.f;
#pragma unroll
    for (int l = 0; l < PL; l++) {
        const float4* wp = (const float4*)(w + l * PH + h0);
        float4 wa = wp[0], wb = wp[1];
        float m, s;
        m = wa.x * va.x; s = m * m;
        m = wa.y * va.y; s = fmaf(m, m, s);
        m = wa.z * va.z; s = fmaf(m, m, s);
        m = wa.w * va.w; s = fmaf(m, m, s);
        m = wb.x * vb.x; s = fmaf(m, m, s);
        m = wb.y * vb.y; s = fmaf(m, m, s);
        m = wb.z * vb.z; s = fmaf(m, m, s);
        m = wb.w * vb.w; s = fmaf(m, m, s);
        s += __shfl_xor_sync(0xffffffffu, s, 16);
        s += __shfl_xor_sync(0xffffffffu, s, 8);
        s += __shfl_xor_sync(0xffffffffu, s, 4);
        s += __shfl_xor_sync(0xffffffffu, s, 2);
        s += __shfl_xor_sync(0xffffffffu, s, 1);
        if (lid == l) keep = s;
    }
    if (lid < PL) op[(size_t)idx * PL + lid] = rsqrtf(keep);
}

// ===================== kernel 2: main fused GEMM (mma.sync tf32) =====================
// CTA(b, it, nt): out[b, it*128.., nt*256..], N axis = (j*16 + l).
//   A  = v1 tile, tf32 in smem [128][KPAD], K-chunked, double-buffered
//   B" = (w^2 (.) v2) chunk, tf32 in smem [KC][NPAD] (k-major), double-buffered
//   Warp tile 64x64 (acc 128 regs). Epilogue scales by rn1[i,l]*rn2[n].

// smem float offsets
static constexpr uint32_t FO_A0  = 0;                          // 128*36 = 4608
static constexpr uint32_t FO_A1  = FO_A0 + TILE_M * KPAD;      // 4608
static constexpr uint32_t FO_B0  = FO_A1 + TILE_M * KPAD;      // 32*264 = 8448
static constexpr uint32_t FO_B1  = FO_B0 + KC * NPAD;
static constexpr uint32_t FO_V2  = FO_B1 + KC * NPAD;          // 16*260 = 4160
static constexpr uint32_t FO_W2T = FO_V2 + 16 * 260;           // 256*16 = 4096 (transposed)
static constexpr uint32_t FO_RN1 = FO_W2T + PH * PL;           // 128*16 = 2048
static constexpr uint32_t FO_RN2 = FO_RN1 + TILE_M * PL;       // 256
static constexpr uint32_t SMEM_FLOATS = FO_RN2 + TILE_N;
static constexpr uint32_t SMEM_BYTES  = SMEM_FLOATS * 4;       // ~147 KB < 227 KB

__global__ void __launch_bounds__(256, 1)
matching_mma(const float* __restrict__ v1, const float* __restrict__ v2,
             const float* __restrict__ w, float* __restrict__ out) {
    extern __shared__ float sm[];

    const int tid = threadIdx.x;
    const int wid = tid >> 5;
    const int lid = tid & 31;
    const int bb  = blockIdx.z;
    const int it  = blockIdx.y;
    const int nt  = blockIdx.x;

    const int iw = (wid >> 2) * 64;   // warp row offset (2 rows of warps)
    const int nw = (wid & 3) * 64;    // warp col offset (4 cols of warps)

    float* v2s  = sm + FO_V2;    // [16][260]
    float* w2t  = sm + FO_W2T;   // [256][16]  (transposed w^2)
    float* rn1s = sm + FO_RN1;   // [128][16]
    float* rn2s = sm + FO_RN2;   // [256]

    const int j0 = nt * 16;      // first j row of this n-tile

    // ---- stage raw operands ----
    // w^2 transposed: w2t[m][l] = w[l][m]^2   (one-time scatter, cost negligible)
    for (int idx = tid; idx < PL * PH; idx += 256) {
        int l = idx >> 8, m = idx & 255;
        float t = w[l * PH + m];
        w2t[m * PL + l] = t * t;
    }
    // v2 rows for this n-tile: 16 x 256
    for (int idx = tid; idx < 16 * (PH / 4); idx += 256) {
        int jj = idx >> 6, h4 = idx & 63;
        float4 t = ((const float4*)(v2 + ((size_t)(bb * PS + j0 + jj)) * PH))[h4];
        *(float4*)&v2s[jj * 260 + h4 * 4] = t;
    }
    // rn1 tile: 2048 contiguous floats
    {
        const float4* src = (const float4*)(g_rn1 + ((size_t)(bb * PS + it * TILE_M)) * PL);
        ((float4*)rn1s)[tid]       = src[tid];
        ((float4*)rn1s)[tid + 256] = src[tid + 256];
    }
    // rn2 tile: 256 contiguous floats
    if (tid < 64) {
        ((float4*)rn2s)[tid] = ((const float4*)(g_rn2 + ((size_t)(bb * PS + j0)) * PL))[tid];
    }
    __syncthreads();

    const float* v1base = v1 + ((size_t)(bb * PS + it * TILE_M)) * PH;

    // ---- chunk builders ----
    // A chunk: [128 rows][KC] tf32, KPAD stride. 1024 float4, 4 per thread.
    auto buildA = [&](int kc, uint32_t* dst) {
        const int hbase = kc * KC;
#pragma unroll
        for (int t = 0; t < 4; t++) {
            int g = tid + t * 256;          // 0..1023
            int i = g >> 3;                 // 128 rows (8 float4 per row)
            int k = (g & 7) * 4;            // 0..28
            float4 s = *(const float4*)(v1base + (size_t)i * PH + hbase + k);
            uint4 u;
            u.x = f2tf32(s.x); u.y = f2tf32(s.y); u.z = f2tf32(s.z); u.w = f2tf32(s.w);
            *(uint4*)(dst + i * KPAD + k) = u;
        }
    };
    // B" chunk: [KC k][256 n] tf32 (k-major), n = jj*16 + l. 2048 float4, 8/thread.
    auto buildB = [&](int kc, uint32_t* dst) {
        const int hbase = kc * KC;
#pragma unroll
        for (int t = 0; t < 8; t++) {
            int g  = tid + t * 256;         // 0..2047
            int k  = g >> 6;                // 0..31 (64 float4 per k-row)
            int n0 = (g & 63) * 4;          // 0..252
            int jj = n0 >> 4;               // 0..15
            int l0 = n0 & 15;               // 0,4,8,12 (l contiguous within float4)
            int m  = hbase + k;
            float  a = v2s[jj * 260 + m];                 // broadcast scalar LDS
            float4 q = *(const float4*)&w2t[m * PL + l0]; // vector LDS, conflict-free
            uint4 u;
            u.x = f2tf32(a * q.x);
            u.y = f2tf32(a * q.y);
            u.z = f2tf32(a * q.z);
            u.w = f2tf32(a * q.w);
            *(uint4*)(dst + k * NPAD + n0) = u;
        }
    };

    // build stage 0
    buildA(0, (uint32_t*)(sm + FO_A0));
    buildB(0, (uint32_t*)(sm + FO_B0));
    __syncthreads();

    float acc[4][8][4];
#pragma unroll
    for (int mf = 0; mf < 4; mf++)
#pragma unroll
        for (int nf = 0; nf < 8; nf++)
#pragma unroll
            for (int q = 0; q < 4; q++) acc[mf][nf][q] = 0.f;

    const int arow = lid >> 2;   // 0..7
    const int acol = lid & 3;    // 0..3

    for (int kc = 0; kc < NKC; kc++) {
        const int cur = kc & 1;
        // build next chunk first (LDG/FFMA/STS overlap the LDS/MMA below)
        if (kc + 1 < NKC) {
            buildA(kc + 1, (uint32_t*)(sm + (cur ? FO_A0 : FO_A1)));
            buildB(kc + 1, (uint32_t*)(sm + (cur ? FO_B0 : FO_B1)));
        }
        const uint32_t* As = (const uint32_t*)(sm + (cur ? FO_A1 : FO_A0));
        const uint32_t* Bs = (const uint32_t*)(sm + (cur ? FO_B1 : FO_B0));

#pragma unroll
        for (int ks = 0; ks < KC / 8; ks++) {
            const int k0 = ks * 8;
            uint32_t af[4][4];
#pragma unroll
            for (int mf = 0; mf < 4; mf++) {
                const int r = iw + mf * 16 + arow;
                const int c = k0 + acol;
                af[mf][0] = As[r * KPAD + c];
                af[mf][1] = As[(r + 8) * KPAD + c];
                af[mf][2] = As[r * KPAD + c + 4];
                af[mf][3] = As[(r + 8) * KPAD + c + 4];
            }
#pragma unroll
            for (int nf = 0; nf < 8; nf++) {
                const int cn = nw + nf * 8 + arow;
                uint32_t b0 = Bs[(k0 + acol) * NPAD + cn];
                uint32_t b1 = Bs[(k0 + 4 + acol) * NPAD + cn];
                mma_tf32(acc[0][nf], af[0], b0, b1);
                mma_tf32(acc[1][nf], af[1], b0, b1);
                mma_tf32(acc[2][nf], af[2], b0, b1);
                mma_tf32(acc[3][nf], af[3], b0, b1);
            }
        }
        __syncthreads();
    }

    // ---- epilogue: scale by rn1[i,l] * rn2[n], coalesced float2 stores ----
    {
        const size_t orow0 = (size_t)(bb * PS + it * TILE_M);
        float* obase = out + orow0 * (size_t)(PS * PL) + (size_t)nt * TILE_N;
#pragma unroll
        for (int mf = 0; mf < 4; mf++) {
            const int r0 = iw + mf * 16 + arow;       // local i (and r0+8)
#pragma unroll
            for (int nf = 0; nf < 8; nf++) {
                const int cn = nw + nf * 8 + 2 * acol;  // local n (even)
                const float s2x = rn2s[cn];
                const float s2y = rn2s[cn + 1];
                const int lx = cn & 15, ly = (cn + 1) & 15;
                {
                    const float r1x = rn1s[r0 * 16 + lx];
                    const float r1y = rn1s[r0 * 16 + ly];
                    float2 o;
                    o.x = acc[mf][nf][0] * r1x * s2x;
                    o.y = acc[mf][nf][1] * r1y * s2y;
                    *(float2*)(obase + (size_t)r0 * (PS * PL) + cn) = o;
                }
                {
                    const int r1r = r0 + 8;
                    const float r1x = rn1s[r1r * 16 + lx];
                    const float r1y = rn1s[r1r * 16 + ly];
                    float2 o;
                    o.x = acc[mf][nf][2] * r1x * s2x;
                    o.y = acc[mf][nf][3] * r1y * s2y;
                    *(float2*)(obase + (size_t)r1r * (PS * PL) + cn) = o;
                }
            }
        }
    }
}

// ===================== launch =====================
extern "C" void kernel_launch(void* const* d_in, const int* in_sizes, int n_in,
                              void* d_out, int out_size) {
    const float* v1 = (const float*)d_in[0];
    const float* v2 = (const float*)d_in[1];
    const float* w  = (const float*)d_in[2];
    float* out = (float*)d_out;

    cudaFuncSetAttribute(matching_mma,
                         cudaFuncAttributeMaxDynamicSharedMemorySize, SMEM_BYTES);

    // 2 * PB * PS = 16384 warps, 8 warps per block
    rnorm_kernel<<<2048, 256>>>(v1, v2, w);

    dim3 grid(NT, IT, PB);
    matching_mma<<<grid, 256, SMEM_BYTES>>>(v1, v2, w, out);
}

// round 9
// speedup vs baseline: 1.1468x; 1.1085x over previous
#include <cuda_runtime.h>
#include <cstdint>

// ===================== problem constants =====================
static constexpr int PB = 16;    // batch
static constexpr int PS = 512;   // S1 = S2
static constexpr int PH = 256;   // hidden
static constexpr int PL = 16;    // perspectives

// main-kernel tiling
static constexpr int TILE_M = 128;                 // i rows per CTA
static constexpr int TILE_N = 256;                 // (j,l) cols per CTA = 16 j * 16 l
static constexpr int KC     = 32;                  // K chunk
static constexpr int NKC    = PH / KC;             // 8 chunks
static constexpr int NT     = (PS * PL) / TILE_N;  // 32 n-tiles
static constexpr int IT     = PS / TILE_M;         // 4 i-tiles
static constexpr int NTHREADS = 512;               // 16 warps, 4 per SMSP

static constexpr int KPAD = 36;    // A row stride: (36%32=4) -> frag loads conflict-free
static constexpr int NPAD = 264;   // B row stride: (264%32=8) -> frag loads conflict-free

// scratch for reciprocal weighted norms (device globals: allocation-free)
__device__ float g_rn1[PB * PS * PL];
__device__ float g_rn2[PB * PS * PL];

// ===================== helpers =====================
__device__ __forceinline__ uint32_t f2tf32(float x) {
    uint32_t r;
    asm("cvt.rna.tf32.f32 %0, %1;" : "=r"(r) : "f"(x));
    return r;
}

// m16n8k8 tf32 MMA, D += A*B (fragments per PTX ISA mapping)
__device__ __forceinline__ void mma_tf32(float* c, const uint32_t* a,
                                         uint32_t b0, uint32_t b1) {
    asm volatile(
        "mma.sync.aligned.m16n8k8.row.col.f32.tf32.tf32.f32 "
        "{%0,%1,%2,%3}, {%4,%5,%6,%7}, {%8,%9}, {%0,%1,%2,%3};\n"
        : "+f"(c[0]), "+f"(c[1]), "+f"(c[2]), "+f"(c[3])
        : "r"(a[0]), "r"(a[1]), "r"(a[2]), "r"(a[3]), "r"(b0), "r"(b1));
}

// ===================== kernel 1: reciprocal weighted norms =====================
// one warp per (tensor, b, s): rn[b,s,l] = rsqrt( sum_h (w[l,h]*v[b,s,h])^2 )
__global__ __launch_bounds__(256) void rnorm_kernel(const float* __restrict__ v1,
                                                    const float* __restrict__ v2,
                                                    const float* __restrict__ w) {
    int gw  = blockIdx.x * 8 + (threadIdx.x >> 5);   // 0 .. 16383
    int lid = threadIdx.x & 31;
    const float* v  = (gw < PB * PS) ? v1 : v2;
    float*       op = (gw < PB * PS) ? g_rn1 : g_rn2;
    int idx = gw & (PB * PS - 1);                    // b*512 + s
    int h0  = lid * 8;

    const float4* vp = (const float4*)(v + (size_t)idx * PH + h0);
    float4 va = vp[0], vb = vp[1];

    float keep = 0.f;
#pragma unroll
    for (int l = 0; l < PL; l++) {
        const float4* wp = (const float4*)(w + l * PH + h0);
        float4 wa = wp[0], wb = wp[1];
        float m, s;
        m = wa.x * va.x; s = m * m;
        m = wa.y * va.y; s = fmaf(m, m, s);
        m = wa.z * va.z; s = fmaf(m, m, s);
        m = wa.w * va.w; s = fmaf(m, m, s);
        m = wb.x * vb.x; s = fmaf(m, m, s);
        m = wb.y * vb.y; s = fmaf(m, m, s);
        m = wb.z * vb.z; s = fmaf(m, m, s);
        m = wb.w * vb.w; s = fmaf(m, m, s);
        s += __shfl_xor_sync(0xffffffffu, s, 16);
        s += __shfl_xor_sync(0xffffffffu, s, 8);
        s += __shfl_xor_sync(0xffffffffu, s, 4);
        s += __shfl_xor_sync(0xffffffffu, s, 2);
        s += __shfl_xor_sync(0xffffffffu, s, 1);
        if (lid == l) keep = s;
    }
    if (lid < PL) op[(size_t)idx * PL + lid] = rsqrtf(keep);
}

// ===================== kernel 2: main fused GEMM (mma.sync tf32) =====================
// CTA(b, it, nt): out[b, it*128.., nt*256..], N axis = (j*16 + l).
//   512 threads, 16 warps in 4x4 grid, warp tile 32x64 (acc 64 regs).
//   A  = v1 tile, tf32 in smem [128][KPAD], K-chunked, double-buffered
//   B" = (w^2 (.) v2) chunk, tf32 in smem [KC][NPAD] (k-major), double-buffered
//   Epilogue scales by rn1[i,l]*rn2[n], coalesced float2 stores.

// smem float offsets
static constexpr uint32_t FO_A0  = 0;                          // 128*36 = 4608
static constexpr uint32_t FO_A1  = FO_A0 + TILE_M * KPAD;      // 4608
static constexpr uint32_t FO_B0  = FO_A1 + TILE_M * KPAD;      // 32*264 = 8448
static constexpr uint32_t FO_B1  = FO_B0 + KC * NPAD;
static constexpr uint32_t FO_V2  = FO_B1 + KC * NPAD;          // 16*260 = 4160
static constexpr uint32_t FO_W2T = FO_V2 + 16 * 260;           // 256*16 = 4096 (transposed)
static constexpr uint32_t FO_RN1 = FO_W2T + PH * PL;           // 128*16 = 2048
static constexpr uint32_t FO_RN2 = FO_RN1 + TILE_M * PL;       // 256
static constexpr uint32_t SMEM_FLOATS = FO_RN2 + TILE_N;
static constexpr uint32_t SMEM_BYTES  = SMEM_FLOATS * 4;       // ~147 KB < 227 KB

__global__ void __launch_bounds__(NTHREADS, 1)
matching_mma(const float* __restrict__ v1, const float* __restrict__ v2,
             const float* __restrict__ w, float* __restrict__ out) {
    extern __shared__ float sm[];

    const int tid = threadIdx.x;
    const int wid = tid >> 5;
    const int lid = tid & 31;
    const int bb  = blockIdx.z;
    const int it  = blockIdx.y;
    const int nt  = blockIdx.x;

    const int iw = (wid >> 2) * 32;   // warp row offset (4 row-groups of 32)
    const int nw = (wid & 3) * 64;    // warp col offset (4 col-groups of 64)

    float* v2s  = sm + FO_V2;    // [16][260]
    float* w2t  = sm + FO_W2T;   // [256][16]  (transposed w^2)
    float* rn1s = sm + FO_RN1;   // [128][16]
    float* rn2s = sm + FO_RN2;   // [256]

    const int j0 = nt * 16;      // first j row of this n-tile

    // ---- stage raw operands ----
    // w^2 transposed: w2t[m][l] = w[l][m]^2
    for (int idx = tid; idx < PL * PH; idx += NTHREADS) {
        int l = idx >> 8, m = idx & 255;
        float t = w[l * PH + m];
        w2t[m * PL + l] = t * t;
    }
    // v2 rows for this n-tile: 16 x 256
    for (int idx = tid; idx < 16 * (PH / 4); idx += NTHREADS) {
        int jj = idx >> 6, h4 = idx & 63;
        float4 t = ((const float4*)(v2 + ((size_t)(bb * PS + j0 + jj)) * PH))[h4];
        *(float4*)&v2s[jj * 260 + h4 * 4] = t;
    }
    // rn1 tile: 2048 contiguous floats = 512 float4
    {
        const float4* src = (const float4*)(g_rn1 + ((size_t)(bb * PS + it * TILE_M)) * PL);
        ((float4*)rn1s)[tid] = src[tid];
    }
    // rn2 tile: 256 contiguous floats
    if (tid < 64) {
        ((float4*)rn2s)[tid] = ((const float4*)(g_rn2 + ((size_t)(bb * PS + j0)) * PL))[tid];
    }
    __syncthreads();

    const float* v1base = v1 + ((size_t)(bb * PS + it * TILE_M)) * PH;

    // ---- chunk builders ----
    // A chunk: [128 rows][KC] tf32, KPAD stride. 1024 float4, 2 per thread.
    auto buildA = [&](int kc, uint32_t* dst) {
        const int hbase = kc * KC;
#pragma unroll
        for (int t = 0; t < 2; t++) {
            int g = tid + t * NTHREADS;     // 0..1023
            int i = g >> 3;                 // 128 rows (8 float4 per row)
            int k = (g & 7) * 4;            // 0..28
            float4 s = *(const float4*)(v1base + (size_t)i * PH + hbase + k);
            uint4 u;
            u.x = f2tf32(s.x); u.y = f2tf32(s.y); u.z = f2tf32(s.z); u.w = f2tf32(s.w);
            *(uint4*)(dst + i * KPAD + k) = u;
        }
    };
    // B" chunk: [KC k][256 n] tf32 (k-major), n = jj*16 + l. 2048 float4, 4/thread.
    auto buildB = [&](int kc, uint32_t* dst) {
        const int hbase = kc * KC;
#pragma unroll
        for (int t = 0; t < 4; t++) {
            int g  = tid + t * NTHREADS;    // 0..2047
            int k  = g >> 6;                // 0..31 (64 float4 per k-row)
            int n0 = (g & 63) * 4;          // 0..252
            int jj = n0 >> 4;               // 0..15
            int l0 = n0 & 15;               // 0,4,8,12 (l contiguous within float4)
            int m  = hbase + k;
            float  a = v2s[jj * 260 + m];                 // broadcast scalar LDS
            float4 q = *(const float4*)&w2t[m * PL + l0]; // vector LDS, conflict-free
            uint4 u;
            u.x = f2tf32(a * q.x);
            u.y = f2tf32(a * q.y);
            u.z = f2tf32(a * q.z);
            u.w = f2tf32(a * q.w);
            *(uint4*)(dst + k * NPAD + n0) = u;
        }
    };

    // build stage 0
    buildA(0, (uint32_t*)(sm + FO_A0));
    buildB(0, (uint32_t*)(sm + FO_B0));
    __syncthreads();

    float acc[2][8][4];
#pragma unroll
    for (int mf = 0; mf < 2; mf++)
#pragma unroll
        for (int nf = 0; nf < 8; nf++)
#pragma unroll
            for (int q = 0; q < 4; q++) acc[mf][nf][q] = 0.f;

    const int arow = lid >> 2;   // 0..7
    const int acol = lid & 3;    // 0..3

    for (int kc = 0; kc < NKC; kc++) {
        const int cur = kc & 1;
        // build next chunk first (LDG/FFMA/STS overlap the LDS/MMA below)
        if (kc + 1 < NKC) {
            buildA(kc + 1, (uint32_t*)(sm + (cur ? FO_A0 : FO_A1)));
            buildB(kc + 1, (uint32_t*)(sm + (cur ? FO_B0 : FO_B1)));
        }
        const uint32_t* As = (const uint32_t*)(sm + (cur ? FO_A1 : FO_A0));
        const uint32_t* Bs = (const uint32_t*)(sm + (cur ? FO_B1 : FO_B0));

#pragma unroll
        for (int ks = 0; ks < KC / 8; ks++) {
            const int k0 = ks * 8;
            uint32_t af[2][4];
#pragma unroll
            for (int mf = 0; mf < 2; mf++) {
                const int r = iw + mf * 16 + arow;
                const int c = k0 + acol;
                af[mf][0] = As[r * KPAD + c];
                af[mf][1] = As[(r + 8) * KPAD + c];
                af[mf][2] = As[r * KPAD + c + 4];
                af[mf][3] = As[(r + 8) * KPAD + c + 4];
            }
#pragma unroll
            for (int nf = 0; nf < 8; nf++) {
                const int cn = nw + nf * 8 + arow;
                uint32_t b0 = Bs[(k0 + acol) * NPAD + cn];
                uint32_t b1 = Bs[(k0 + 4 + acol) * NPAD + cn];
                mma_tf32(acc[0][nf], af[0], b0, b1);
                mma_tf32(acc[1][nf], af[1], b0, b1);
            }
        }
        __syncthreads();
    }

    // ---- epilogue: scale by rn1[i,l] * rn2[n], coalesced float2 stores ----
    {
        const size_t orow0 = (size_t)(bb * PS + it * TILE_M);
        float* obase = out + orow0 * (size_t)(PS * PL) + (size_t)nt * TILE_N;
#pragma unroll
        for (int mf = 0; mf < 2; mf++) {
            const int r0 = iw + mf * 16 + arow;       // local i (and r0+8)
#pragma unroll
            for (int nf = 0; nf < 8; nf++) {
                const int cn = nw + nf * 8 + 2 * acol;  // local n (even)
                const float s2x = rn2s[cn];
                const float s2y = rn2s[cn + 1];
                const int lx = cn & 15, ly = (cn + 1) & 15;
                {
                    const float r1x = rn1s[r0 * 16 + lx];
                    const float r1y = rn1s[r0 * 16 + ly];
                    float2 o;
                    o.x = acc[mf][nf][0] * r1x * s2x;
                    o.y = acc[mf][nf][1] * r1y * s2y;
                    *(float2*)(obase + (size_t)r0 * (PS * PL) + cn) = o;
                }
                {
                    const int r1r = r0 + 8;
                    const float r1x = rn1s[r1r * 16 + lx];
                    const float r1y = rn1s[r1r * 16 + ly];
                    float2 o;
                    o.x = acc[mf][nf][2] * r1x * s2x;
                    o.y = acc[mf][nf][3] * r1y * s2y;
                    *(float2*)(obase + (size_t)r1r * (PS * PL) + cn) = o;
                }
            }
        }
    }
}

// ===================== launch =====================
extern "C" void kernel_launch(void* const* d_in, const int* in_sizes, int n_in,
                              void* d_out, int out_size) {
    const float* v1 = (const float*)d_in[0];
    const float* v2 = (const float*)d_in[1];
    const float* w  = (const float*)d_in[2];
    float* out = (float*)d_out;

    cudaFuncSetAttribute(matching_mma,
                         cudaFuncAttributeMaxDynamicSharedMemorySize, SMEM_BYTES);

    // 2 * PB * PS = 16384 warps, 8 warps per block
    rnorm_kernel<<<2048, 256>>>(v1, v2, w);

    dim3 grid(NT, IT, PB);
    matching_mma<<<grid, NTHREADS, SMEM_BYTES>>>(v1, v2, w, out);
}

// round 10
// speedup vs baseline: 1.1529x; 1.0054x over previous
#include <cuda_runtime.h>
#include <cstdint>

// ===================== problem constants =====================
static constexpr int PB = 16;    // batch
static constexpr int PS = 512;   // S1 = S2
static constexpr int PH = 256;   // hidden
static constexpr int PL = 16;    // perspectives

// main-kernel tiling
static constexpr int TILE_M = 128;                 // i rows per CTA
static constexpr int TILE_N = 256;                 // (j,l) cols per CTA = 16 j * 16 l
static constexpr int KC     = 32;                  // K chunk
static constexpr int NKC    = PH / KC;             // 8 chunks
static constexpr int NT     = (PS * PL) / TILE_N;  // 32 n-tiles
static constexpr int IT     = PS / TILE_M;         // 4 i-tiles
static constexpr int NTHREADS = 512;               // 16 warps, 4 per SMSP

static constexpr int KPAD = 36;    // A row stride: (36%32=4) -> frag loads conflict-free
static constexpr int NPAD = 264;   // B row stride: (264%32=8) -> frag loads conflict-free

// scratch for reciprocal weighted norms (device globals: allocation-free)
__device__ float g_rn1[PB * PS * PL];
__device__ float g_rn2[PB * PS * PL];

// ===================== helpers =====================
__device__ __forceinline__ uint32_t f2tf32(float x) {
    uint32_t r;
    asm("cvt.rna.tf32.f32 %0, %1;" : "=r"(r) : "f"(x));
    return r;
}

// m16n8k8 tf32 MMA, D += A*B (fragments per PTX ISA mapping)
__device__ __forceinline__ void mma_tf32(float* c, const uint32_t* a,
                                         uint32_t b0, uint32_t b1) {
    asm volatile(
        "mma.sync.aligned.m16n8k8.row.col.f32.tf32.tf32.f32 "
        "{%0,%1,%2,%3}, {%4,%5,%6,%7}, {%8,%9}, {%0,%1,%2,%3};\n"
        : "+f"(c[0]), "+f"(c[1]), "+f"(c[2]), "+f"(c[3])
        : "r"(a[0]), "r"(a[1]), "r"(a[2]), "r"(a[3]), "r"(b0), "r"(b1));
}

// ===================== kernel 1: reciprocal weighted norms =====================
// one warp per (tensor, b, s): rn[b,s,l] = rsqrt( sum_h (w[l,h]*v[b,s,h])^2 )
__global__ __launch_bounds__(256) void rnorm_kernel(const float* __restrict__ v1,
                                                    const float* __restrict__ v2,
                                                    const float* __restrict__ w) {
    int gw  = blockIdx.x * 8 + (threadIdx.x >> 5);   // 0 .. 16383
    int lid = threadIdx.x & 31;
    const float* v  = (gw < PB * PS) ? v1 : v2;
    float*       op = (gw < PB * PS) ? g_rn1 : g_rn2;
    int idx = gw & (PB * PS - 1);                    // b*512 + s
    int h0  = lid * 8;

    const float4* vp = (const float4*)(v + (size_t)idx * PH + h0);
    float4 va = vp[0], vb = vp[1];

    float keep = 0.f;
#pragma unroll
    for (int l = 0; l < PL; l++) {
        const float4* wp = (const float4*)(w + l * PH + h0);
        float4 wa = wp[0], wb = wp[1];
        float m, s;
        m = wa.x * va.x; s = m * m;
        m = wa.y * va.y; s = fmaf(m, m, s);
        m = wa.z * va.z; s = fmaf(m, m, s);
        m = wa.w * va.w; s = fmaf(m, m, s);
        m = wb.x * vb.x; s = fmaf(m, m, s);
        m = wb.y * vb.y; s = fmaf(m, m, s);
        m = wb.z * vb.z; s = fmaf(m, m, s);
        m = wb.w * vb.w; s = fmaf(m, m, s);
        s += __shfl_xor_sync(0xffffffffu, s, 16);
        s += __shfl_xor_sync(0xffffffffu, s, 8);
        s += __shfl_xor_sync(0xffffffffu, s, 4);
        s += __shfl_xor_sync(0xffffffffu, s, 2);
        s += __shfl_xor_sync(0xffffffffu, s, 1);
        if (lid == l) keep = s;
    }
    if (lid < PL) op[(size_t)idx * PL + lid] = rsqrtf(keep);
}

// ===================== kernel 2: main fused GEMM (mma.sync tf32) =====================
// CTA(b, it, nt): out[b, it*128.., nt*256..], N axis = (j*16 + l).
//   512 threads, 16 warps in 4x4 grid, warp tile 32x64 (acc 64 regs).
//   A  = v1 tile, tf32 in smem [128][KPAD], K-chunked, double-buffered
//   B" = (w^2 (.) v2) chunk, tf32 in smem [KC][NPAD] (k-major), double-buffered
//   Epilogue scales by rn1[i,l]*rn2[n], coalesced float2 stores.

// smem float offsets
static constexpr uint32_t FO_A0  = 0;                          // 128*36 = 4608
static constexpr uint32_t FO_A1  = FO_A0 + TILE_M * KPAD;      // 4608
static constexpr uint32_t FO_B0  = FO_A1 + TILE_M * KPAD;      // 32*264 = 8448
static constexpr uint32_t FO_B1  = FO_B0 + KC * NPAD;
static constexpr uint32_t FO_V2  = FO_B1 + KC * NPAD;          // 16*260 = 4160
static constexpr uint32_t FO_W2T = FO_V2 + 16 * 260;           // 256*16 = 4096 (transposed)
static constexpr uint32_t FO_RN1 = FO_W2T + PH * PL;           // 128*16 = 2048
static constexpr uint32_t FO_RN2 = FO_RN1 + TILE_M * PL;       // 256
static constexpr uint32_t SMEM_FLOATS = FO_RN2 + TILE_N;
static constexpr uint32_t SMEM_BYTES  = SMEM_FLOATS * 4;       // ~147 KB < 227 KB

__global__ void __launch_bounds__(NTHREADS, 1)
matching_mma(const float* __restrict__ v1, const float* __restrict__ v2,
             const float* __restrict__ w, float* __restrict__ out) {
    extern __shared__ float sm[];

    const int tid = threadIdx.x;
    const int wid = tid >> 5;
    const int lid = tid & 31;
    const int bb  = blockIdx.z;
    const int it  = blockIdx.y;
    const int nt  = blockIdx.x;

    const int iw = (wid >> 2) * 32;   // warp row offset (4 row-groups of 32)
    const int nw = (wid & 3) * 64;    // warp col offset (4 col-groups of 64)

    float* v2s  = sm + FO_V2;    // [16][260]
    float* w2t  = sm + FO_W2T;   // [256][16]  (transposed w^2)
    float* rn1s = sm + FO_RN1;   // [128][16]
    float* rn2s = sm + FO_RN2;   // [256]

    const int j0 = nt * 16;      // first j row of this n-tile

    // ---- stage raw operands ----
    // w^2 transposed: w2t[m][l] = w[l][m]^2
    for (int idx = tid; idx < PL * PH; idx += NTHREADS) {
        int l = idx >> 8, m = idx & 255;
        float t = w[l * PH + m];
        w2t[m * PL + l] = t * t;
    }
    // v2 rows for this n-tile: 16 x 256
    for (int idx = tid; idx < 16 * (PH / 4); idx += NTHREADS) {
        int jj = idx >> 6, h4 = idx & 63;
        float4 t = ((const float4*)(v2 + ((size_t)(bb * PS + j0 + jj)) * PH))[h4];
        *(float4*)&v2s[jj * 260 + h4 * 4] = t;
    }
    // rn1 tile: 2048 contiguous floats = 512 float4
    {
        const float4* src = (const float4*)(g_rn1 + ((size_t)(bb * PS + it * TILE_M)) * PL);
        ((float4*)rn1s)[tid] = src[tid];
    }
    // rn2 tile: 256 contiguous floats
    if (tid < 64) {
        ((float4*)rn2s)[tid] = ((const float4*)(g_rn2 + ((size_t)(bb * PS + j0)) * PL))[tid];
    }
    __syncthreads();

    const float* v1base = v1 + ((size_t)(bb * PS + it * TILE_M)) * PH;

    // ---- chunk builders ----
    // A chunk: [128 rows][KC] tf32, KPAD stride. 1024 float4, 2 per thread.
    auto buildA = [&](int kc, uint32_t* dst) {
        const int hbase = kc * KC;
#pragma unroll
        for (int t = 0; t < 2; t++) {
            int g = tid + t * NTHREADS;     // 0..1023
            int i = g >> 3;                 // 128 rows (8 float4 per row)
            int k = (g & 7) * 4;            // 0..28
            float4 s = *(const float4*)(v1base + (size_t)i * PH + hbase + k);
            uint4 u;
            u.x = f2tf32(s.x); u.y = f2tf32(s.y); u.z = f2tf32(s.z); u.w = f2tf32(s.w);
            *(uint4*)(dst + i * KPAD + k) = u;
        }
    };
    // B" chunk: [KC k][256 n] tf32 (k-major), n = jj*16 + l. 2048 float4, 4/thread.
    auto buildB = [&](int kc, uint32_t* dst) {
        const int hbase = kc * KC;
#pragma unroll
        for (int t = 0; t < 4; t++) {
            int g  = tid + t * NTHREADS;    // 0..2047
            int k  = g >> 6;                // 0..31 (64 float4 per k-row)
            int n0 = (g & 63) * 4;          // 0..252
            int jj = n0 >> 4;               // 0..15
            int l0 = n0 & 15;               // 0,4,8,12 (l contiguous within float4)
            int m  = hbase + k;
            float  a = v2s[jj * 260 + m];                 // broadcast scalar LDS
            float4 q = *(const float4*)&w2t[m * PL + l0]; // vector LDS, conflict-free
            uint4 u;
            u.x = f2tf32(a * q.x);
            u.y = f2tf32(a * q.y);
            u.z = f2tf32(a * q.z);
            u.w = f2tf32(a * q.w);
            *(uint4*)(dst + k * NPAD + n0) = u;
        }
    };

    // build stage 0
    buildA(0, (uint32_t*)(sm + FO_A0));
    buildB(0, (uint32_t*)(sm + FO_B0));
    __syncthreads();

    float acc[2][8][4];
#pragma unroll
    for (int mf = 0; mf < 2; mf++)
#pragma unroll
        for (int nf = 0; nf < 8; nf++)
#pragma unroll
            for (int q = 0; q < 4; q++) acc[mf][nf][q] = 0.f;

    const int arow = lid >> 2;   // 0..7
    const int acol = lid & 3;    // 0..3

    for (int kc = 0; kc < NKC; kc++) {
        const int cur = kc & 1;
        // build next chunk first (LDG/FFMA/STS overlap the LDS/MMA below)
        if (kc + 1 < NKC) {
            buildA(kc + 1, (uint32_t*)(sm + (cur ? FO_A0 : FO_A1)));
            buildB(kc + 1, (uint32_t*)(sm + (cur ? FO_B0 : FO_B1)));
        }
        const uint32_t* As = (const uint32_t*)(sm + (cur ? FO_A1 : FO_A0));
        const uint32_t* Bs = (const uint32_t*)(sm + (cur ? FO_B1 : FO_B0));

#pragma unroll
        for (int ks = 0; ks < KC / 8; ks++) {
            const int k0 = ks * 8;
            uint32_t af[2][4];
#pragma unroll
            for (int mf = 0; mf < 2; mf++) {
                const int r = iw + mf * 16 + arow;
                const int c = k0 + acol;
                af[mf][0] = As[r * KPAD + c];
                af[mf][1] = As[(r + 8) * KPAD + c];
                af[mf][2] = As[r * KPAD + c + 4];
                af[mf][3] = As[(r + 8) * KPAD + c + 4];
            }
#pragma unroll
            for (int nf = 0; nf < 8; nf++) {
                const int cn = nw + nf * 8 + arow;
                uint32_t b0 = Bs[(k0 + acol) * NPAD + cn];
                uint32_t b1 = Bs[(k0 + 4 + acol) * NPAD + cn];
                mma_tf32(acc[0][nf], af[0], b0, b1);
                mma_tf32(acc[1][nf], af[1], b0, b1);
            }
        }
        __syncthreads();
    }

    // ---- epilogue: scale by rn1[i,l] * rn2[n], coalesced float2 stores ----
    {
        const size_t orow0 = (size_t)(bb * PS + it * TILE_M);
        float* obase = out + orow0 * (size_t)(PS * PL) + (size_t)nt * TILE_N;
#pragma unroll
        for (int mf = 0; mf < 2; mf++) {
            const int r0 = iw + mf * 16 + arow;       // local i (and r0+8)
#pragma unroll
            for (int nf = 0; nf < 8; nf++) {
                const int cn = nw + nf * 8 + 2 * acol;  // local n (even)
                const float s2x = rn2s[cn];
                const float s2y = rn2s[cn + 1];
                const int lx = cn & 15, ly = (cn + 1) & 15;
                {
                    const float r1x = rn1s[r0 * 16 + lx];
                    const float r1y = rn1s[r0 * 16 + ly];
                    float2 o;
                    o.x = acc[mf][nf][0] * r1x * s2x;
                    o.y = acc[mf][nf][1] * r1y * s2y;
                    *(float2*)(obase + (size_t)r0 * (PS * PL) + cn) = o;
                }
                {
                    const int r1r = r0 + 8;
                    const float r1x = rn1s[r1r * 16 + lx];
                    const float r1y = rn1s[r1r * 16 + ly];
                    float2 o;
                    o.x = acc[mf][nf][2] * r1x * s2x;
                    o.y = acc[mf][nf][3] * r1y * s2y;
                    *(float2*)(obase + (size_t)r1r * (PS * PL) + cn) = o;
                }
            }
        }
    }
}

// ===================== launch =====================
extern "C" void kernel_launch(void* const* d_in, const int* in_sizes, int n_in,
                              void* d_out, int out_size) {
    const float* v1 = (const float*)d_in[0];
    const float* v2 = (const float*)d_in[1];
    const float* w  = (const float*)d_in[2];
    float* out = (float*)d_out;

    cudaFuncSetAttribute(matching_mma,
                         cudaFuncAttributeMaxDynamicSharedMemorySize, SMEM_BYTES);

    // 2 * PB * PS = 16384 warps, 8 warps per block
    rnorm_kernel<<<2048, 256>>>(v1, v2, w);

    dim3 grid(NT, IT, PB);
    matching_mma<<<grid, NTHREADS, SMEM_BYTES>>>(v1, v2, w, out);
}